// round 9
// baseline (speedup 1.0000x reference)
#include <cuda_runtime.h>
#include <cuda_fp16.h>
#include <math.h>
#include <stdint.h>

#define Bc   16
#define Sc   256
#define Dc   256
#define Hc   128
#define DKc  64
#define NIN  512
#define NJ   1024
#define GRP  8
#define NCH  16
#define CHS  16

// wgemm config
#define NIT    16
#define STG_A  8192
#define STAGE  16384
// pool-gemm config
#define PSTAGE 12288

// ---------------- scratch -----------------
__device__ float g_xtT[Bc * DKc * Sc];
__device__ float g_U[Sc * Bc * NJ];
__device__ float g_cend[NCH * 32 * Hc];
__device__ float g_P[NCH * 32 * Hc];
__device__ float g_yt[Bc * Sc * DKc];                  // [b][s][k]
__device__ __align__(256) __half g_Ah[Sc * Bc * NIN];  // rows ++ pools (fp16)
__device__ __align__(256) __half g_Wh[2 * NJ * NIN];   // [layer][n][k]
__device__ __align__(256) __half g_w2h[8 * DKc * Dc];  // [a][k][d]
__device__ __align__(256) __half g_att[Bc * Sc * Sc];  // [b][s][l]
__device__ __align__(256) __half g_xh[Bc * Sc * Dc];   // x as fp16

// ---------------- helpers -----------------
__device__ __forceinline__ float tanh_fast(float x) {
    float y; asm("tanh.approx.f32 %0, %1;" : "=f"(y) : "f"(x)); return y;
}
__device__ __forceinline__ __half2 tanh2_fast(__half2 x) {
    uint32_t xi = *reinterpret_cast<uint32_t*>(&x), yi;
    asm("tanh.approx.f16x2 %0, %1;" : "=r"(yi) : "r"(xi));
    return *reinterpret_cast<__half2*>(&yi);
}
__device__ __forceinline__ __half2 as_h2(uint32_t u) {
    return *reinterpret_cast<__half2*>(&u);
}
__device__ __forceinline__ float sig_fast(float x) {
    float e, r;
    asm("ex2.approx.f32 %0, %1;" : "=f"(e) : "f"(x * -1.4426950408889634f));
    asm("rcp.approx.f32 %0, %1;" : "=f"(r) : "f"(1.0f + e));
    return r;
}
__device__ __forceinline__ uint32_t smem_u32(const void* p) {
    uint32_t a;
    asm("{ .reg .u64 t; cvta.to.shared.u64 t, %1; cvt.u32.u64 %0, t; }" : "=r"(a) : "l"(p));
    return a;
}
__device__ __forceinline__ void cp16(uint32_t d, const void* s) {
    asm volatile("cp.async.cg.shared.global [%0], [%1], 16;\n" :: "r"(d), "l"(s));
}
#define CP_COMMIT() asm volatile("cp.async.commit_group;\n" ::: "memory")
#define CP_WAIT2()  asm volatile("cp.async.wait_group 2;\n" ::: "memory")

__device__ __forceinline__ void ldsm4(uint32_t* r, uint32_t addr) {
    asm volatile("ldmatrix.sync.aligned.m8n8.x4.shared.b16 {%0,%1,%2,%3}, [%4];"
                 : "=r"(r[0]), "=r"(r[1]), "=r"(r[2]), "=r"(r[3]) : "r"(addr));
}
__device__ __forceinline__ void ldsm4t(uint32_t* r, uint32_t addr) {
    asm volatile("ldmatrix.sync.aligned.m8n8.x4.trans.shared.b16 {%0,%1,%2,%3}, [%4];"
                 : "=r"(r[0]), "=r"(r[1]), "=r"(r[2]), "=r"(r[3]) : "r"(addr));
}
__device__ __forceinline__ void mma16816(float* c, const uint32_t* a, const uint32_t* b) {
    asm volatile("mma.sync.aligned.m16n8k16.row.col.f32.f16.f16.f32 "
                 "{%0,%1,%2,%3}, {%4,%5,%6,%7}, {%8,%9}, {%0,%1,%2,%3};"
                 : "+f"(c[0]), "+f"(c[1]), "+f"(c[2]), "+f"(c[3])
                 : "r"(a[0]), "r"(a[1]), "r"(a[2]), "r"(a[3]), "r"(b[0]), "r"(b[1]));
}

// ---------------------------------------------------------------------------
// x -> fp16 (g_xh), and layer-0 rows into g_Ah
// ---------------------------------------------------------------------------
__global__ void k_xconv(const float* __restrict__ x) {
    const int e = (blockIdx.x * 256 + threadIdx.x) * 4;
    float4 v = *reinterpret_cast<const float4*>(x + e);
    __half2 h0 = __floats2half2_rn(v.x, v.y);
    __half2 h1 = __floats2half2_rn(v.z, v.w);
    *reinterpret_cast<__half2*>(&g_xh[e])     = h0;
    *reinterpret_cast<__half2*>(&g_xh[e + 2]) = h1;
    const int b = e >> 16, s = (e >> 8) & 255, d = e & 255;
    const size_t idx = (size_t)(s * Bc + b) * NIN + d;
    *reinterpret_cast<__half2*>(&g_Ah[idx])     = h0;
    *reinterpret_cast<__half2*>(&g_Ah[idx + 2]) = h1;
}

// ---------------------------------------------------------------------------
// SRU weight convert+transpose: g_Wh[(l*1024+n)*512+k]
// ---------------------------------------------------------------------------
__global__ void k_wconv(const float* __restrict__ wf, const float* __restrict__ wb) {
    const int k0 = blockIdx.x * 32, nt = blockIdx.y * 32, l = blockIdx.z;
    const float* W = (nt < 512) ? (wf + l * 262144 + nt) : (wb + l * 262144 + (nt - 512));
    __shared__ float t[32][33];
    const int tx = threadIdx.x, ty = threadIdx.y;
    for (int i = ty; i < 32; i += 8)
        t[i][tx] = W[(k0 + i) * 512 + tx];
    __syncthreads();
    for (int i = ty; i < 32; i += 8) {
        size_t idx = (size_t)(l * NJ + nt + i) * NIN + k0 + tx;
        g_Wh[idx] = __float2half(t[tx][i]);
    }
}

// ---------------------------------------------------------------------------
// w2 convert+transpose: g_w2h[a][k][d] from w2[a][d][k]
// ---------------------------------------------------------------------------
__global__ void k_w2conv(const float* __restrict__ w2) {
    const int a = blockIdx.x, dt = blockIdx.y;
    __shared__ float t[32][65];
    const int tid = threadIdx.x;
    for (int i = tid; i < 2048; i += 256) {
        int d = i >> 6, kk = i & 63;
        t[d][kk] = w2[((size_t)a * Dc + dt * 32 + d) * DKc + kk];
    }
    __syncthreads();
    for (int i = tid; i < 2048; i += 256) {
        int kk = i >> 5, d = i & 31;
        g_w2h[((size_t)a * DKc + kk) * Dc + dt * 32 + d] = __float2half(t[d][kk]);
    }
}

// ---------------------------------------------------------------------------
// xtT[b][k][l] = b1[a,k] + sum_d x[b,l,d]*w1[a,d,k]  (once, fp32)
// ---------------------------------------------------------------------------
__global__ void k_xt(const float* __restrict__ x, const float* __restrict__ w1,
                     const float* __restrict__ b1, const int* __restrict__ act) {
    const int b = blockIdx.x, lt = blockIdx.y;
    const int a = act[b];
    const float* xb = x + b * Sc * Dc + lt * 64 * Dc;
    const float* wa = w1 + a * Dc * DKc;
    __shared__ float xs[32][65];
    __shared__ float ws[32][64];
    const int tid = threadIdx.x;
    const int ty = tid >> 4, tx = tid & 15;
    float acc[4][4] = {};
    for (int d0 = 0; d0 < Dc; d0 += 32) {
        for (int i = tid; i < 64 * 32; i += 256) {
            int l = i >> 5, d = i & 31;
            xs[d][l] = xb[l * Dc + d0 + d];
        }
        for (int i = tid; i < 32 * 64; i += 256) {
            int d = i >> 6, k = i & 63;
            ws[d][k] = wa[(d0 + d) * DKc + k];
        }
        __syncthreads();
#pragma unroll
        for (int d = 0; d < 32; d++) {
            float af[4], bfv[4];
#pragma unroll
            for (int i = 0; i < 4; i++) af[i] = xs[d][ty * 4 + i];
#pragma unroll
            for (int j = 0; j < 4; j++) bfv[j] = ws[d][tx * 4 + j];
#pragma unroll
            for (int i = 0; i < 4; i++)
#pragma unroll
                for (int j = 0; j < 4; j++) acc[i][j] = fmaf(af[i], bfv[j], acc[i][j]);
        }
        __syncthreads();
    }
#pragma unroll
    for (int j = 0; j < 4; j++) {
        int k = tx * 4 + j;
        float bb = b1[a * DKc + k];
#pragma unroll
        for (int i = 0; i < 4; i++) {
            int l = lt * 64 + ty * 4 + i;
            g_xtT[b * (DKc * Sc) + k * Sc + l] = acc[i][j] + bb;
        }
    }
}

// ---------------------------------------------------------------------------
// yt GEMV: g_yt[b][s][k] = b2[a,k] + sum_d rows[s][d] * w2[a][d][k]
// rows read fp16 from g_Ah. grid (16 b, 8 st of 32 rows), 256 threads.
// Warp lanes share (part,s8) -> smem row reads are pure broadcast.
// ---------------------------------------------------------------------------
__global__ void __launch_bounds__(256) k_yt(const int* __restrict__ act,
                                            const float* __restrict__ b2) {
    const int b = blockIdx.x, st = blockIdx.y;
    const int a = act[b];
    const int tid = threadIdx.x;
    __shared__ __align__(16) __half rows[32][256];

    for (int i = tid; i < 1024; i += 256) {
        int r = i >> 5, c = i & 31;
        const uint4* src = reinterpret_cast<const uint4*>(
            g_Ah + (size_t)((st * 32 + r) * Bc + b) * NIN + c * 8);
        *reinterpret_cast<uint4*>(&rows[r][c * 8]) = *src;
    }
    __syncthreads();

    const int k = tid & 63, part = tid >> 6;
    const __half* wk = g_w2h + (size_t)(a * DKc + k) * Dc;
    const float bb = b2[a * DKc + k];
    float accf[8] = {};

    for (int d0 = 0; d0 < 256; d0 += 32) {
        uint4 w0 = *reinterpret_cast<const uint4*>(wk + d0);
        uint4 w1 = *reinterpret_cast<const uint4*>(wk + d0 + 8);
        uint4 w2q = *reinterpret_cast<const uint4*>(wk + d0 + 16);
        uint4 w3 = *reinterpret_cast<const uint4*>(wk + d0 + 24);
        uint32_t wv[16] = {w0.x, w0.y, w0.z, w0.w, w1.x, w1.y, w1.z, w1.w,
                           w2q.x, w2q.y, w2q.z, w2q.w, w3.x, w3.y, w3.z, w3.w};
#pragma unroll
        for (int s8 = 0; s8 < 8; s8++) {
            const __half* rp = &rows[part * 8 + s8][d0];
            uint4 r0 = *reinterpret_cast<const uint4*>(rp);
            uint4 r1 = *reinterpret_cast<const uint4*>(rp + 8);
            uint4 r2 = *reinterpret_cast<const uint4*>(rp + 16);
            uint4 r3 = *reinterpret_cast<const uint4*>(rp + 24);
            uint32_t rv[16] = {r0.x, r0.y, r0.z, r0.w, r1.x, r1.y, r1.z, r1.w,
                               r2.x, r2.y, r2.z, r2.w, r3.x, r3.y, r3.z, r3.w};
            __half2 acc2 = __float2half2_rn(0.0f);
#pragma unroll
            for (int j = 0; j < 16; j++)
                acc2 = __hfma2(as_h2(rv[j]), as_h2(wv[j]), acc2);
            float2 f = __half22float2(acc2);
            accf[s8] += f.x + f.y;
        }
    }
#pragma unroll
    for (int s8 = 0; s8 < 8; s8++) {
        int s = st * 32 + part * 8 + s8;
        g_yt[((size_t)b * Sc + s) * DKc + k] = accf[s8] + bb;
    }
}

// ---------------------------------------------------------------------------
// Attention scores+softmax only: reads g_yt + g_xtT, writes g_att.
// ---------------------------------------------------------------------------
__global__ void __launch_bounds__(256) k_attn(
        const unsigned char* __restrict__ mask,
        const int* __restrict__ act,
        const float* __restrict__ v) {
    const int s0 = blockIdx.x * GRP;
    const int b = blockIdx.y;
    const int a = act[b];
    const int tid = threadIdx.x;

    __shared__ __align__(8) __half2 yt2h[DKc][4];   // [k][g-pair]
    __shared__ __half2 vv2[DKc];
    __shared__ float red[8][GRP];
    __shared__ float ginv[GRP];

    const bool msk = mask[b * Sc + tid];
    if (tid < DKc) vv2[tid] = __float2half2_rn(v[a * DKc + tid]);
    {
        int k = tid >> 2, j = tid & 3;
        float y0 = g_yt[((size_t)b * Sc + s0 + 2 * j) * DKc + k];
        float y1 = g_yt[((size_t)b * Sc + s0 + 2 * j + 1) * DKc + k];
        yt2h[k][j] = __floats2half2_rn(y0, y1);
    }
    __syncthreads();

    // scores: l = tid, fp16x2 tanh, 8-k chunked half2 accum -> fp32
    float sc[GRP] = {};
    {
        const float* xt = g_xtT + b * (DKc * Sc);
        for (int k0 = 0; k0 < DKc; k0 += 8) {
            float xvv[8];
#pragma unroll
            for (int kk = 0; kk < 8; kk++)
                xvv[kk] = xt[(k0 + kk) * Sc + tid];
            __half2 acc2[4];
#pragma unroll
            for (int j = 0; j < 4; j++) acc2[j] = __float2half2_rn(0.0f);
#pragma unroll
            for (int kk = 0; kk < 8; kk++) {
                const int k = k0 + kk;
                const __half2 xv2 = __float2half2_rn(xvv[kk]);
                const __half2 vk2 = vv2[k];
#pragma unroll
                for (int j = 0; j < 4; j++) {
                    __half2 t = tanh2_fast(__hadd2(xv2, yt2h[k][j]));
                    acc2[j] = __hfma2(vk2, t, acc2[j]);
                }
            }
#pragma unroll
            for (int j = 0; j < 4; j++) {
                float2 f = __half22float2(acc2[j]);
                sc[j * 2]     += f.x;
                sc[j * 2 + 1] += f.y;
            }
        }
    }

    // softmax without max-subtraction (|score| <= sum|v| <= 8)
    const int lane = tid & 31, wid = tid >> 5;
    float ex[GRP];
#pragma unroll
    for (int g = 0; g < GRP; g++) ex[g] = msk ? 0.0f : __expf(sc[g]);
#pragma unroll
    for (int g = 0; g < GRP; g++) {
        float s = ex[g];
#pragma unroll
        for (int o = 16; o > 0; o >>= 1) s += __shfl_xor_sync(0xffffffffu, s, o);
        if (lane == 0) red[wid][g] = s;
    }
    __syncthreads();
    if (tid < GRP) {
        float s = red[0][tid];
#pragma unroll
        for (int w = 1; w < 8; w++) s += red[w][tid];
        ginv[tid] = 1.0f / s;
    }
    __syncthreads();

#pragma unroll
    for (int g = 0; g < GRP; g++)
        g_att[((size_t)b * Sc + s0 + g) * Sc + tid] = __float2half(ex[g] * ginv[g]);
}

// ---------------------------------------------------------------------------
// Pools GEMM: pools = att @ x (HMMA), writes fp16 into g_Ah[...,256+d]
// ---------------------------------------------------------------------------
__device__ __forceinline__ void p_load(int c, int tid, uint32_t sb,
                                       int b, int st, int nt) {
    const int l0 = c << 5;
    const uint32_t ab = sb + (c % 3) * PSTAGE;
    const uint32_t bb = ab + 4096;
    {
        int r = tid >> 2, ch = tid & 3;
        const __half* src = g_att + ((size_t)b * Sc + st * 64 + r) * Sc + l0 + ch * 8;
        cp16(ab + r * 64 + ((ch ^ (r & 3)) << 4), src);
    }
#pragma unroll
    for (int i = 0; i < 2; i++) {
        int v = tid + i * 256, r = v >> 4, ch = v & 15;
        const __half* src = g_xh + ((size_t)b * Sc + l0 + r) * Dc + nt * 128 + ch * 8;
        cp16(bb + r * 256 + ((ch ^ (r & 15)) << 4), src);
    }
}

__global__ void __launch_bounds__(256) k_pool() {
    __shared__ __align__(128) char sm[3 * PSTAGE];
    const uint32_t sb = smem_u32(sm);
    const int tid = threadIdx.x, wid = tid >> 5, lane = tid & 31;
    const int b = blockIdx.x, st = blockIdx.y, nt = blockIdx.z;
    const int wm = wid & 1, wn = wid >> 1;

    float acc[2][4][4] = {};

    p_load(0, tid, sb, b, st, nt); CP_COMMIT();
    p_load(1, tid, sb, b, st, nt); CP_COMMIT();

    for (int c = 0; c < 8; c++) {
        if (c + 2 < 8) p_load(c + 2, tid, sb, b, st, nt);
        CP_COMMIT();
        CP_WAIT2();
        __syncthreads();

        const uint32_t ab = sb + (c % 3) * PSTAGE;
        const uint32_t bb = ab + 4096;
#pragma unroll
        for (int ks = 0; ks < 2; ks++) {
            uint32_t a[2][4];
#pragma unroll
            for (int mt2 = 0; mt2 < 2; mt2++) {
                int r = wm * 32 + mt2 * 16 + (lane & 15);
                int k8 = ks * 2 + (lane >> 4);
                ldsm4(a[mt2], ab + r * 64 + ((k8 ^ (r & 3)) << 4));
            }
            uint32_t bf[4][2];
#pragma unroll
            for (int ng = 0; ng < 2; ng++) {
                int r = ks * 16 + (lane & 15);
                int ch = wn * 4 + ng * 2 + (lane >> 4);
                uint32_t t[4];
                ldsm4t(t, bb + r * 256 + ((ch ^ (r & 15)) << 4));
                bf[ng * 2][0] = t[0]; bf[ng * 2][1] = t[1];
                bf[ng * 2 + 1][0] = t[2]; bf[ng * 2 + 1][1] = t[3];
            }
#pragma unroll
            for (int mt2 = 0; mt2 < 2; mt2++)
#pragma unroll
                for (int oct = 0; oct < 4; oct++)
                    mma16816(acc[mt2][oct], a[mt2], bf[oct]);
        }
        __syncthreads();
    }

    const int s_b = st * 64 + wm * 32 + (lane >> 2);
    const int d_b = nt * 128 + wn * 32 + (lane & 3) * 2;
#pragma unroll
    for (int mt2 = 0; mt2 < 2; mt2++) {
#pragma unroll
        for (int oct = 0; oct < 4; oct++) {
            int s = s_b + mt2 * 16, d = d_b + oct * 8;
            __half2 h01 = __floats2half2_rn(acc[mt2][oct][0], acc[mt2][oct][1]);
            __half2 h23 = __floats2half2_rn(acc[mt2][oct][2], acc[mt2][oct][3]);
            *reinterpret_cast<__half2*>(&g_Ah[(size_t)(s * Bc + b) * NIN + Dc + d]) = h01;
            *reinterpret_cast<__half2*>(&g_Ah[(size_t)((s + 8) * Bc + b) * NIN + Dc + d]) = h23;
        }
    }
}

// ---------------------------------------------------------------------------
// HMMA GEMM: U = Ah @ Wh^T
// ---------------------------------------------------------------------------
__device__ __forceinline__ void g_load(int c, int tid, uint32_t sb,
                                       int mt, int nt, int layer) {
    const int kc = c << 5;
    const __half* Ap = g_Ah + (size_t)(mt * 128) * NIN + kc;
    const __half* Bp = g_Wh + (size_t)(layer * NJ + nt * 128) * NIN + kc;
    const uint32_t ab = sb + (c % 3) * STAGE;
    const uint32_t bb = ab + STG_A;
#pragma unroll
    for (int i = 0; i < 2; i++) {
        int vi = tid + i * 256, r = vi >> 2, ch = vi & 3;
        cp16(ab + r * 64 + ((ch ^ (r & 3)) << 4), Ap + (size_t)r * NIN + ch * 8);
    }
#pragma unroll
    for (int i = 0; i < 2; i++) {
        int vi = tid + i * 256, r = vi >> 2, ch = vi & 3;
        cp16(bb + r * 64 + ((ch ^ (r & 3)) << 4), Bp + (size_t)r * NIN + ch * 8);
    }
}

__global__ void __launch_bounds__(256) k_wgemm(int layer) {
    __shared__ __align__(128) char sm[3 * STAGE];
    const uint32_t sb = smem_u32(sm);
    const int tid = threadIdx.x, wid = tid >> 5, lane = tid & 31;
    const int mt = blockIdx.x, nt = blockIdx.y;
    const int wm = wid & 3, wn = wid >> 2;

    float acc[2][8][4] = {};

    g_load(0, tid, sb, mt, nt, layer); CP_COMMIT();
    g_load(1, tid, sb, mt, nt, layer); CP_COMMIT();

    const int arow_b = wm * 32 + (lane & 15);
    const int brow_b = wn * 64 + (lane & 15);
    const int khalf = lane >> 4;

    for (int c = 0; c < NIT; c++) {
        if (c + 2 < NIT) g_load(c + 2, tid, sb, mt, nt, layer);
        CP_COMMIT();
        CP_WAIT2();
        __syncthreads();

        const uint32_t ab = sb + (c % 3) * STAGE;
        const uint32_t bb = ab + STG_A;
#pragma unroll
        for (int ks = 0; ks < 2; ks++) {
            const int k8 = ks * 2 + khalf;
            uint32_t a[2][4], b[8][2];
#pragma unroll
            for (int mtile = 0; mtile < 2; mtile++) {
                int r = arow_b + mtile * 16;
                ldsm4(a[mtile], ab + r * 64 + ((k8 ^ (r & 3)) << 4));
            }
#pragma unroll
            for (int np = 0; np < 4; np++) {
                int r = brow_b + np * 16;
                uint32_t t[4];
                ldsm4(t, bb + r * 64 + ((k8 ^ (r & 3)) << 4));
                b[np * 2][0] = t[0]; b[np * 2 + 1][0] = t[1];
                b[np * 2][1] = t[2]; b[np * 2 + 1][1] = t[3];
            }
#pragma unroll
            for (int mtile = 0; mtile < 2; mtile++)
#pragma unroll
                for (int ntile = 0; ntile < 8; ntile++)
                    mma16816(acc[mtile][ntile], a[mtile], b[ntile]);
        }
        __syncthreads();
    }

    const int m_b = mt * 128 + wm * 32 + (lane >> 2);
    const int n_b = nt * 128 + wn * 64 + (lane & 3) * 2;
#pragma unroll
    for (int mtile = 0; mtile < 2; mtile++) {
#pragma unroll
        for (int ntile = 0; ntile < 8; ntile++) {
            float* dst = g_U + (size_t)(m_b + mtile * 16) * NJ + n_b + ntile * 8;
            *reinterpret_cast<float2*>(dst) =
                make_float2(acc[mtile][ntile][0], acc[mtile][ntile][1]);
            *reinterpret_cast<float2*>(dst + 8 * NJ) =
                make_float2(acc[mtile][ntile][2], acc[mtile][ntile][3]);
        }
    }
}

// ---------------------------------------------------------------------------
// SRU chunked-parallel scan with batched prefetch
// ---------------------------------------------------------------------------
__global__ void k_scanA(const float* __restrict__ bfv, const float* __restrict__ bbv,
                        int layer) {
    const int ch = blockIdx.x, by = blockIdx.y;
    const int b = by >> 1, dir = by & 1;
    const int h = threadIdx.x;
    const float bf = ((dir == 0 ? bfv : bbv) + layer * 2 * Hc)[h];
    const float* base = g_U + ((size_t)(ch * CHS) * Bc + b) * NJ + dir * 512 + h;

    float u0v[CHS], ufv[CHS];
#pragma unroll
    for (int s = 0; s < CHS; s++) {
        const float* u = base + (size_t)s * (Bc * NJ);
        u0v[s] = u[0];
        ufv[s] = u[128];
    }
    float c = 0.0f, P = 1.0f;
#pragma unroll
    for (int s = 0; s < CHS; s++) {
        float f = sig_fast(ufv[s] + bf);
        c = u0v[s] + f * (c - u0v[s]);
        P *= f;
    }
    const int idx = (ch * 32 + by) * Hc + h;
    g_cend[idx] = c;
    g_P[idx] = P;
}

__global__ void k_scanC(const float* __restrict__ bfv, const float* __restrict__ bbv,
                        int layer, int is_last, float* __restrict__ out_final) {
    const int ch = blockIdx.x, by = blockIdx.y;
    const int b = by >> 1, dir = by & 1;
    const int h = threadIdx.x;
    const float* bias = (dir == 0 ? bfv : bbv) + layer * 2 * Hc;
    const float bf = bias[h];
    const float br = bias[Hc + h];
    const float* base = g_U + ((size_t)(ch * CHS) * Bc + b) * NJ + dir * 512 + h;

    float c = 0.0f;
    {
        float Pa[NCH - 1], Ca[NCH - 1];
#pragma unroll
        for (int i = 0; i < NCH - 1; i++) {
            if (i < ch) {
                const int idx = (i * 32 + by) * Hc + h;
                Pa[i] = g_P[idx];
                Ca[i] = g_cend[idx];
            }
        }
#pragma unroll
        for (int i = 0; i < NCH - 1; i++)
            if (i < ch) c = Pa[i] * c + Ca[i];
    }

#pragma unroll
    for (int half = 0; half < 2; half++) {
        float u0v[8], ufv[8], urv[8], hwv[8];
#pragma unroll
        for (int s = 0; s < 8; s++) {
            const float* u = base + (size_t)(half * 8 + s) * (Bc * NJ);
            u0v[s] = u[0]; ufv[s] = u[128]; urv[s] = u[256]; hwv[s] = u[384];
        }
#pragma unroll
        for (int s = 0; s < 8; s++) {
            float f = sig_fast(ufv[s] + bf);
            float r = sig_fast(urv[s] + br);
            c = u0v[s] + f * (c - u0v[s]);
            float hv = hwv[s] + r * (tanh_fast(c) - hwv[s]);
            const int s_abs = ch * CHS + half * 8 + s;
            if (is_last)
                out_final[b * (Sc * Dc) + s_abs * Dc + dir * Hc + h] = hv;
            else
                g_Ah[(size_t)(s_abs * Bc + b) * NIN + dir * Hc + h] = __float2half(hv);
        }
    }
}

// ---------------------------------------------------------------------------
extern "C" void kernel_launch(void* const* d_in, const int* in_sizes, int n_in,
                              void* d_out, int out_size) {
    const float* x            = (const float*)d_in[0];
    const unsigned char* mask = (const unsigned char*)d_in[1];
    const int* act            = (const int*)d_in[2];
    const float* w1           = (const float*)d_in[3];
    const float* b1           = (const float*)d_in[4];
    const float* w2           = (const float*)d_in[5];
    const float* b2           = (const float*)d_in[6];
    const float* v            = (const float*)d_in[7];
    const float* swf          = (const float*)d_in[8];
    const float* sbf          = (const float*)d_in[9];
    const float* swb          = (const float*)d_in[10];
    const float* sbb          = (const float*)d_in[11];
    float* out = (float*)d_out;

    k_xconv<<<Bc * Sc * Dc / 1024, 256>>>(x);
    k_wconv<<<dim3(16, 32, 2), dim3(32, 8)>>>(swf, swb);
    k_w2conv<<<dim3(8, 8), 256>>>(w2);
    k_xt<<<dim3(Bc, 4), 256>>>(x, w1, b1, act);

    for (int layer = 0; layer < 2; layer++) {
        k_yt<<<dim3(Bc, 8), 256>>>(act, b2);
        k_attn<<<dim3(Sc / GRP, Bc), 256>>>(mask, act, v);
        k_pool<<<dim3(Bc, 4, 2), 256>>>();
        k_wgemm<<<dim3(32, 8), 256>>>(layer);
        k_scanA<<<dim3(NCH, 32), Hc>>>(sbf, sbb, layer);
        k_scanC<<<dim3(NCH, 32), Hc>>>(sbf, sbb, layer, layer == 1 ? 1 : 0, out);
    }
}

// round 10
// speedup vs baseline: 1.1146x; 1.1146x over previous
#include <cuda_runtime.h>
#include <cuda_fp16.h>
#include <math.h>
#include <stdint.h>

#define Bc   16
#define Sc   256
#define Dc   256
#define Hc   128
#define DKc  64
#define NIN  512
#define NJ   1024
#define GRP  8
#define NCH  16
#define CHS  16

// wgemm config
#define NIT    16
#define STG_A  8192
#define STAGE  16384
// pool-gemm config
#define PSTAGE 12288

// ---------------- scratch -----------------
__device__ float g_xtT[Bc * DKc * Sc];
__device__ float g_out[Sc * Bc * Dc];
__device__ float g_U[Sc * Bc * NJ];
__device__ float g_cend[NCH * 32 * Hc];
__device__ float g_P[NCH * 32 * Hc];
__device__ __align__(256) __half g_Ah[Sc * Bc * NIN];
__device__ __align__(256) __half g_Wh[2 * NJ * NIN];   // [layer][n][k]
__device__ __align__(256) __half g_att[Bc * Sc * Sc];  // [b][s][l] normalized
__device__ __align__(256) __half g_xh[Bc * Sc * Dc];   // x as fp16

// ---------------- helpers -----------------
__device__ __forceinline__ float tanh_fast(float x) {
    float y; asm("tanh.approx.f32 %0, %1;" : "=f"(y) : "f"(x)); return y;
}
__device__ __forceinline__ float sig_fast(float x) {
    float e, r;
    asm("ex2.approx.f32 %0, %1;" : "=f"(e) : "f"(x * -1.4426950408889634f));
    asm("rcp.approx.f32 %0, %1;" : "=f"(r) : "f"(1.0f + e));
    return r;
}
__device__ __forceinline__ uint32_t smem_u32(const void* p) {
    uint32_t a;
    asm("{ .reg .u64 t; cvta.to.shared.u64 t, %1; cvt.u32.u64 %0, t; }" : "=r"(a) : "l"(p));
    return a;
}
__device__ __forceinline__ void cp16(uint32_t d, const void* s) {
    asm volatile("cp.async.cg.shared.global [%0], [%1], 16;\n" :: "r"(d), "l"(s));
}
#define CP_COMMIT() asm volatile("cp.async.commit_group;\n" ::: "memory")
#define CP_WAIT2()  asm volatile("cp.async.wait_group 2;\n" ::: "memory")

__device__ __forceinline__ void ldsm4(uint32_t* r, uint32_t addr) {
    asm volatile("ldmatrix.sync.aligned.m8n8.x4.shared.b16 {%0,%1,%2,%3}, [%4];"
                 : "=r"(r[0]), "=r"(r[1]), "=r"(r[2]), "=r"(r[3]) : "r"(addr));
}
__device__ __forceinline__ void ldsm4t(uint32_t* r, uint32_t addr) {
    asm volatile("ldmatrix.sync.aligned.m8n8.x4.trans.shared.b16 {%0,%1,%2,%3}, [%4];"
                 : "=r"(r[0]), "=r"(r[1]), "=r"(r[2]), "=r"(r[3]) : "r"(addr));
}
__device__ __forceinline__ void mma16816(float* c, const uint32_t* a, const uint32_t* b) {
    asm volatile("mma.sync.aligned.m16n8k16.row.col.f32.f16.f16.f32 "
                 "{%0,%1,%2,%3}, {%4,%5,%6,%7}, {%8,%9}, {%0,%1,%2,%3};"
                 : "+f"(c[0]), "+f"(c[1]), "+f"(c[2]), "+f"(c[3])
                 : "r"(a[0]), "r"(a[1]), "r"(a[2]), "r"(a[3]), "r"(b[0]), "r"(b[1]));
}

// ---------------------------------------------------------------------------
// x -> fp16 copy (once)
// ---------------------------------------------------------------------------
__global__ void k_xconv(const float* __restrict__ x) {
    int i = (blockIdx.x * 256 + threadIdx.x) * 4;
    float4 v = *reinterpret_cast<const float4*>(x + i);
    *reinterpret_cast<__half2*>(&g_xh[i])     = __floats2half2_rn(v.x, v.y);
    *reinterpret_cast<__half2*>(&g_xh[i + 2]) = __floats2half2_rn(v.z, v.w);
}

// ---------------------------------------------------------------------------
// weight convert+transpose
// ---------------------------------------------------------------------------
__global__ void k_wconv(const float* __restrict__ wf, const float* __restrict__ wb) {
    const int k0 = blockIdx.x * 32, nt = blockIdx.y * 32, l = blockIdx.z;
    const float* W = (nt < 512) ? (wf + l * 262144 + nt) : (wb + l * 262144 + (nt - 512));
    __shared__ float t[32][33];
    const int tx = threadIdx.x, ty = threadIdx.y;
    for (int i = ty; i < 32; i += 8)
        t[i][tx] = W[(k0 + i) * 512 + tx];
    __syncthreads();
    for (int i = ty; i < 32; i += 8) {
        size_t idx = (size_t)(l * NJ + nt + i) * NIN + k0 + tx;
        g_Wh[idx] = __float2half(t[tx][i]);
    }
}

// ---------------------------------------------------------------------------
// xtT[b][k][l] = b1[a,k] + sum_d x[b,l,d]*w1[a,d,k]
// 256 blocks (16 b x 16 l-tiles of 16 rows), BK=64, 4 outputs/thread.
// Latency-focused: tiny tile, high block count, broadcast smem reads.
// ---------------------------------------------------------------------------
__global__ void __launch_bounds__(256) k_xt(
        const float* __restrict__ x, const float* __restrict__ w1,
        const float* __restrict__ b1, const int* __restrict__ act) {
    const int b = blockIdx.x, lt = blockIdx.y;
    const int a = act[b];
    const float* xb = x + b * Sc * Dc + lt * 16 * Dc;
    const float* wa = w1 + a * Dc * DKc;

    __shared__ float xs[16][65];   // [l][d-chunk]
    __shared__ float ws[64][64];   // [d][k]

    const int tid = threadIdx.x;
    const int k = tid & 63, lg = tid >> 6;   // 4 l-groups of 4
    float acc[4] = {};

#pragma unroll
    for (int d0 = 0; d0 < Dc; d0 += 64) {
        // stage x tile: 16 x 64
#pragma unroll
        for (int i = 0; i < 4; i++) {
            int v = tid + i * 256, l = v >> 6, d = v & 63;
            xs[l][d] = xb[l * Dc + d0 + d];
        }
        // stage w tile: 64 x 64
#pragma unroll
        for (int i = 0; i < 16; i++) {
            int v = tid + i * 256, d = v >> 6, kk = v & 63;
            ws[d][kk] = wa[(d0 + d) * DKc + kk];
        }
        __syncthreads();
#pragma unroll 8
        for (int d = 0; d < 64; d++) {
            float w = ws[d][k];
#pragma unroll
            for (int i = 0; i < 4; i++)
                acc[i] = fmaf(xs[lg * 4 + i][d], w, acc[i]);
        }
        __syncthreads();
    }
    const float bb = b1[a * DKc + k];
#pragma unroll
    for (int i = 0; i < 4; i++) {
        int l = lt * 16 + lg * 4 + i;
        g_xtT[b * (DKc * Sc) + k * Sc + l] = acc[i] + bb;
    }
}

// ---------------------------------------------------------------------------
// Attention scores+softmax (round-7 version): fused gemv, fp32 tanh scores,
// no-max softmax. Writes rows (fp16) + att matrix (fp16).
// ---------------------------------------------------------------------------
__global__ void __launch_bounds__(256) k_attn(
        const float* __restrict__ x, int layer0,
        const unsigned char* __restrict__ mask,
        const int* __restrict__ act,
        const float* __restrict__ w2, const float* __restrict__ b2,
        const float* __restrict__ v) {
    const int s0 = blockIdx.x * GRP;
    const int b = blockIdx.y;
    const int a = act[b];
    const int tid = threadIdx.x;

    __shared__ float row[GRP][Dc];
    __shared__ __align__(16) float yt2[DKc][GRP];
    __shared__ float vv[DKc];
    __shared__ float ytp[4][GRP][DKc];
    __shared__ float red[8][GRP];
    __shared__ float ginv[GRP];

    const bool msk = mask[b * Sc + tid];

    {
        float rv[GRP];
#pragma unroll
        for (int g = 0; g < GRP; g++) {
            int s = s0 + g;
            rv[g] = layer0 ? x[b * Sc * Dc + s * Dc + tid]
                           : g_out[(s * Bc + b) * Dc + tid];
        }
#pragma unroll
        for (int g = 0; g < GRP; g++) {
            row[g][tid] = rv[g];
            g_Ah[(size_t)((s0 + g) * Bc + b) * NIN + tid] = __float2half(rv[g]);
        }
    }
    if (tid < DKc) vv[tid] = v[a * DKc + tid];
    __syncthreads();

    {
        const float* wa = w2 + a * Dc * DKc;
        const int k = tid & 63, part = tid >> 6;
        float acc[GRP] = {};
        for (int i0 = 0; i0 < 64; i0 += 8) {
            float wv[8];
#pragma unroll
            for (int j = 0; j < 8; j++)
                wv[j] = wa[(part * 64 + i0 + j) * DKc + k];
#pragma unroll
            for (int j = 0; j < 8; j++) {
                int d = part * 64 + i0 + j;
#pragma unroll
                for (int g = 0; g < GRP; g++)
                    acc[g] = fmaf(row[g][d], wv[j], acc[g]);
            }
        }
#pragma unroll
        for (int g = 0; g < GRP; g++) ytp[part][g][k] = acc[g];
    }
    __syncthreads();
    for (int idx = tid; idx < GRP * DKc; idx += 256) {
        int g = idx >> 6, k = idx & 63;
        yt2[k][g] = ytp[0][g][k] + ytp[1][g][k] + ytp[2][g][k] + ytp[3][g][k]
                  + b2[a * DKc + k];
    }
    __syncthreads();

    float sc[GRP] = {};
    {
        const float* xt = g_xtT + b * (DKc * Sc);
        for (int k0 = 0; k0 < DKc; k0 += 8) {
            float xvv[8];
#pragma unroll
            for (int kk = 0; kk < 8; kk++)
                xvv[kk] = xt[(k0 + kk) * Sc + tid];
#pragma unroll
            for (int kk = 0; kk < 8; kk++) {
                const int k = k0 + kk;
                const float vk = vv[k];
                const float xv = xvv[kk];
                float4 y0 = *reinterpret_cast<const float4*>(&yt2[k][0]);
                float4 y1 = *reinterpret_cast<const float4*>(&yt2[k][4]);
                sc[0] = fmaf(vk, tanh_fast(xv + y0.x), sc[0]);
                sc[1] = fmaf(vk, tanh_fast(xv + y0.y), sc[1]);
                sc[2] = fmaf(vk, tanh_fast(xv + y0.z), sc[2]);
                sc[3] = fmaf(vk, tanh_fast(xv + y0.w), sc[3]);
                sc[4] = fmaf(vk, tanh_fast(xv + y1.x), sc[4]);
                sc[5] = fmaf(vk, tanh_fast(xv + y1.y), sc[5]);
                sc[6] = fmaf(vk, tanh_fast(xv + y1.z), sc[6]);
                sc[7] = fmaf(vk, tanh_fast(xv + y1.w), sc[7]);
            }
        }
    }

    // softmax without max-subtraction (|score| <= sum|v| <= 8)
    const int lane = tid & 31, wid = tid >> 5;
    float ex[GRP];
#pragma unroll
    for (int g = 0; g < GRP; g++) ex[g] = msk ? 0.0f : __expf(sc[g]);
#pragma unroll
    for (int g = 0; g < GRP; g++) {
        float s = ex[g];
#pragma unroll
        for (int o = 16; o > 0; o >>= 1) s += __shfl_xor_sync(0xffffffffu, s, o);
        if (lane == 0) red[wid][g] = s;
    }
    __syncthreads();
    if (tid < GRP) {
        float s = red[0][tid];
#pragma unroll
        for (int w = 1; w < 8; w++) s += red[w][tid];
        ginv[tid] = 1.0f / s;
    }
    __syncthreads();

#pragma unroll
    for (int g = 0; g < GRP; g++)
        g_att[((size_t)b * Sc + s0 + g) * Sc + tid] = __float2half(ex[g] * ginv[g]);
}

// ---------------------------------------------------------------------------
// Pools GEMM: pools = att @ x (HMMA), writes fp16 into g_Ah[...,256+d]
// ---------------------------------------------------------------------------
__device__ __forceinline__ void p_load(int c, int tid, uint32_t sb,
                                       int b, int st, int nt) {
    const int l0 = c << 5;
    const uint32_t ab = sb + (c % 3) * PSTAGE;
    const uint32_t bb = ab + 4096;
    {
        int r = tid >> 2, ch = tid & 3;
        const __half* src = g_att + ((size_t)b * Sc + st * 64 + r) * Sc + l0 + ch * 8;
        cp16(ab + r * 64 + ((ch ^ (r & 3)) << 4), src);
    }
#pragma unroll
    for (int i = 0; i < 2; i++) {
        int v = tid + i * 256, r = v >> 4, ch = v & 15;
        const __half* src = g_xh + ((size_t)b * Sc + l0 + r) * Dc + nt * 128 + ch * 8;
        cp16(bb + r * 256 + ((ch ^ (r & 15)) << 4), src);
    }
}

__global__ void __launch_bounds__(256) k_pool() {
    __shared__ __align__(128) char sm[3 * PSTAGE];
    const uint32_t sb = smem_u32(sm);
    const int tid = threadIdx.x, wid = tid >> 5, lane = tid & 31;
    const int b = blockIdx.x, st = blockIdx.y, nt = blockIdx.z;
    const int wm = wid & 1, wn = wid >> 1;

    float acc[2][4][4] = {};

    p_load(0, tid, sb, b, st, nt); CP_COMMIT();
    p_load(1, tid, sb, b, st, nt); CP_COMMIT();

    for (int c = 0; c < 8; c++) {
        if (c + 2 < 8) p_load(c + 2, tid, sb, b, st, nt);
        CP_COMMIT();
        CP_WAIT2();
        __syncthreads();

        const uint32_t ab = sb + (c % 3) * PSTAGE;
        const uint32_t bb = ab + 4096;
#pragma unroll
        for (int ks = 0; ks < 2; ks++) {
            uint32_t a[2][4];
#pragma unroll
            for (int mt2 = 0; mt2 < 2; mt2++) {
                int r = wm * 32 + mt2 * 16 + (lane & 15);
                int k8 = ks * 2 + (lane >> 4);
                ldsm4(a[mt2], ab + r * 64 + ((k8 ^ (r & 3)) << 4));
            }
            uint32_t bf[4][2];
#pragma unroll
            for (int ng = 0; ng < 2; ng++) {
                int r = ks * 16 + (lane & 15);
                int ch = wn * 4 + ng * 2 + (lane >> 4);
                uint32_t t[4];
                ldsm4t(t, bb + r * 256 + ((ch ^ (r & 15)) << 4));
                bf[ng * 2][0] = t[0]; bf[ng * 2][1] = t[1];
                bf[ng * 2 + 1][0] = t[2]; bf[ng * 2 + 1][1] = t[3];
            }
#pragma unroll
            for (int mt2 = 0; mt2 < 2; mt2++)
#pragma unroll
                for (int oct = 0; oct < 4; oct++)
                    mma16816(acc[mt2][oct], a[mt2], bf[oct]);
        }
        __syncthreads();
    }

    const int s_b = st * 64 + wm * 32 + (lane >> 2);
    const int d_b = nt * 128 + wn * 32 + (lane & 3) * 2;
#pragma unroll
    for (int mt2 = 0; mt2 < 2; mt2++) {
#pragma unroll
        for (int oct = 0; oct < 4; oct++) {
            int s = s_b + mt2 * 16, d = d_b + oct * 8;
            __half2 h01 = __floats2half2_rn(acc[mt2][oct][0], acc[mt2][oct][1]);
            __half2 h23 = __floats2half2_rn(acc[mt2][oct][2], acc[mt2][oct][3]);
            *reinterpret_cast<__half2*>(&g_Ah[(size_t)(s * Bc + b) * NIN + Dc + d]) = h01;
            *reinterpret_cast<__half2*>(&g_Ah[(size_t)((s + 8) * Bc + b) * NIN + Dc + d]) = h23;
        }
    }
}

// ---------------------------------------------------------------------------
// HMMA GEMM: U = Ah @ Wh^T
// ---------------------------------------------------------------------------
__device__ __forceinline__ void g_load(int c, int tid, uint32_t sb,
                                       int mt, int nt, int layer) {
    const int kc = c << 5;
    const __half* Ap = g_Ah + (size_t)(mt * 128) * NIN + kc;
    const __half* Bp = g_Wh + (size_t)(layer * NJ + nt * 128) * NIN + kc;
    const uint32_t ab = sb + (c % 3) * STAGE;
    const uint32_t bb = ab + STG_A;
#pragma unroll
    for (int i = 0; i < 2; i++) {
        int vi = tid + i * 256, r = vi >> 2, ch = vi & 3;
        cp16(ab + r * 64 + ((ch ^ (r & 3)) << 4), Ap + (size_t)r * NIN + ch * 8);
    }
#pragma unroll
    for (int i = 0; i < 2; i++) {
        int vi = tid + i * 256, r = vi >> 2, ch = vi & 3;
        cp16(bb + r * 64 + ((ch ^ (r & 3)) << 4), Bp + (size_t)r * NIN + ch * 8);
    }
}

__global__ void __launch_bounds__(256) k_wgemm(int layer) {
    __shared__ __align__(128) char sm[3 * STAGE];
    const uint32_t sb = smem_u32(sm);
    const int tid = threadIdx.x, wid = tid >> 5, lane = tid & 31;
    const int mt = blockIdx.x, nt = blockIdx.y;
    const int wm = wid & 3, wn = wid >> 2;

    float acc[2][8][4] = {};

    g_load(0, tid, sb, mt, nt, layer); CP_COMMIT();
    g_load(1, tid, sb, mt, nt, layer); CP_COMMIT();

    const int arow_b = wm * 32 + (lane & 15);
    const int brow_b = wn * 64 + (lane & 15);
    const int khalf = lane >> 4;

    for (int c = 0; c < NIT; c++) {
        if (c + 2 < NIT) g_load(c + 2, tid, sb, mt, nt, layer);
        CP_COMMIT();
        CP_WAIT2();
        __syncthreads();

        const uint32_t ab = sb + (c % 3) * STAGE;
        const uint32_t bb = ab + STG_A;
#pragma unroll
        for (int ks = 0; ks < 2; ks++) {
            const int k8 = ks * 2 + khalf;
            uint32_t a[2][4], b[8][2];
#pragma unroll
            for (int mtile = 0; mtile < 2; mtile++) {
                int r = arow_b + mtile * 16;
                ldsm4(a[mtile], ab + r * 64 + ((k8 ^ (r & 3)) << 4));
            }
#pragma unroll
            for (int np = 0; np < 4; np++) {
                int r = brow_b + np * 16;
                uint32_t t[4];
                ldsm4(t, bb + r * 64 + ((k8 ^ (r & 3)) << 4));
                b[np * 2][0] = t[0]; b[np * 2 + 1][0] = t[1];
                b[np * 2][1] = t[2]; b[np * 2 + 1][1] = t[3];
            }
#pragma unroll
            for (int mtile = 0; mtile < 2; mtile++)
#pragma unroll
                for (int ntile = 0; ntile < 8; ntile++)
                    mma16816(acc[mtile][ntile], a[mtile], b[ntile]);
        }
        __syncthreads();
    }

    const int m_b = mt * 128 + wm * 32 + (lane >> 2);
    const int n_b = nt * 128 + wn * 64 + (lane & 3) * 2;
#pragma unroll
    for (int mtile = 0; mtile < 2; mtile++) {
#pragma unroll
        for (int ntile = 0; ntile < 8; ntile++) {
            float* dst = g_U + (size_t)(m_b + mtile * 16) * NJ + n_b + ntile * 8;
            *reinterpret_cast<float2*>(dst) =
                make_float2(acc[mtile][ntile][0], acc[mtile][ntile][1]);
            *reinterpret_cast<float2*>(dst + 8 * NJ) =
                make_float2(acc[mtile][ntile][2], acc[mtile][ntile][3]);
        }
    }
}

// ---------------------------------------------------------------------------
// SRU chunked-parallel scan with batched prefetch
// ---------------------------------------------------------------------------
__global__ void k_scanA(const float* __restrict__ bfv, const float* __restrict__ bbv,
                        int layer) {
    const int ch = blockIdx.x, by = blockIdx.y;
    const int b = by >> 1, dir = by & 1;
    const int h = threadIdx.x;
    const float bf = ((dir == 0 ? bfv : bbv) + layer * 2 * Hc)[h];
    const float* base = g_U + ((size_t)(ch * CHS) * Bc + b) * NJ + dir * 512 + h;

    float u0v[CHS], ufv[CHS];
#pragma unroll
    for (int s = 0; s < CHS; s++) {
        const float* u = base + (size_t)s * (Bc * NJ);
        u0v[s] = u[0];
        ufv[s] = u[128];
    }
    float c = 0.0f, P = 1.0f;
#pragma unroll
    for (int s = 0; s < CHS; s++) {
        float f = sig_fast(ufv[s] + bf);
        c = u0v[s] + f * (c - u0v[s]);
        P *= f;
    }
    const int idx = (ch * 32 + by) * Hc + h;
    g_cend[idx] = c;
    g_P[idx] = P;
}

__global__ void k_scanC(const float* __restrict__ bfv, const float* __restrict__ bbv,
                        int layer, int is_last, float* __restrict__ out_final) {
    const int ch = blockIdx.x, by = blockIdx.y;
    const int b = by >> 1, dir = by & 1;
    const int h = threadIdx.x;
    const float* bias = (dir == 0 ? bfv : bbv) + layer * 2 * Hc;
    const float bf = bias[h];
    const float br = bias[Hc + h];
    const float* base = g_U + ((size_t)(ch * CHS) * Bc + b) * NJ + dir * 512 + h;

    float c = 0.0f;
    {
        float Pa[NCH - 1], Ca[NCH - 1];
#pragma unroll
        for (int i = 0; i < NCH - 1; i++) {
            if (i < ch) {
                const int idx = (i * 32 + by) * Hc + h;
                Pa[i] = g_P[idx];
                Ca[i] = g_cend[idx];
            }
        }
#pragma unroll
        for (int i = 0; i < NCH - 1; i++)
            if (i < ch) c = Pa[i] * c + Ca[i];
    }

#pragma unroll
    for (int half = 0; half < 2; half++) {
        float u0v[8], ufv[8], urv[8], hwv[8];
#pragma unroll
        for (int s = 0; s < 8; s++) {
            const float* u = base + (size_t)(half * 8 + s) * (Bc * NJ);
            u0v[s] = u[0]; ufv[s] = u[128]; urv[s] = u[256]; hwv[s] = u[384];
        }
#pragma unroll
        for (int s = 0; s < 8; s++) {
            float f = sig_fast(ufv[s] + bf);
            float r = sig_fast(urv[s] + br);
            c = u0v[s] + f * (c - u0v[s]);
            float hv = hwv[s] + r * (tanh_fast(c) - hwv[s]);
            const int s_abs = ch * CHS + half * 8 + s;
            if (is_last)
                out_final[b * (Sc * Dc) + s_abs * Dc + dir * Hc + h] = hv;
            else
                g_out[(s_abs * Bc + b) * Dc + dir * Hc + h] = hv;
        }
    }
}

// ---------------------------------------------------------------------------
extern "C" void kernel_launch(void* const* d_in, const int* in_sizes, int n_in,
                              void* d_out, int out_size) {
    const float* x            = (const float*)d_in[0];
    const unsigned char* mask = (const unsigned char*)d_in[1];
    const int* act            = (const int*)d_in[2];
    const float* w1           = (const float*)d_in[3];
    const float* b1           = (const float*)d_in[4];
    const float* w2           = (const float*)d_in[5];
    const float* b2           = (const float*)d_in[6];
    const float* v            = (const float*)d_in[7];
    const float* swf          = (const float*)d_in[8];
    const float* sbf          = (const float*)d_in[9];
    const float* swb          = (const float*)d_in[10];
    const float* sbb          = (const float*)d_in[11];
    float* out = (float*)d_out;

    k_xconv<<<Bc * Sc * Dc / 1024, 256>>>(x);
    k_wconv<<<dim3(16, 32, 2), dim3(32, 8)>>>(swf, swb);
    k_xt<<<dim3(Bc, 16), 256>>>(x, w1, b1, act);

    for (int layer = 0; layer < 2; layer++) {
        k_attn<<<dim3(Sc / GRP, Bc), 256>>>(x, layer == 0 ? 1 : 0, mask, act, w2, b2, v);
        k_pool<<<dim3(Bc, 4, 2), 256>>>();
        k_wgemm<<<dim3(32, 8), 256>>>(layer);
        k_scanA<<<dim3(NCH, 32), Hc>>>(sbf, sbb, layer);
        k_scanC<<<dim3(NCH, 32), Hc>>>(sbf, sbb, layer, layer == 1 ? 1 : 0, out);
    }
}